// round 1
// baseline (speedup 1.0000x reference)
#include <cuda_runtime.h>

// GateRecurrent2dnoind: H[h,w] = B*X + G1*H[h-1,w-1] + G2*H[h,w-1] + G3*H[h+1,w-1]
// Shapes: [16, 32, 128, 128] fp32. One CTA per (b,c) plane; thread t = row h.
// Column scan over w runs out of shared memory; global traffic fully coalesced.

#define HH 128
#define WW 128
#define WT 32          // tile width (columns per staged tile)
#define NTILES (WW / WT)
#define PITCH 33       // padded row stride in smem (conflict-free stride-33 reads)

__global__ __launch_bounds__(128, 2)
void gaterec2d_kernel(const float* __restrict__ X,
                      const float* __restrict__ Bg,
                      const float* __restrict__ G1,
                      const float* __restrict__ G2,
                      const float* __restrict__ G3,
                      float* __restrict__ O)
{
    extern __shared__ float sm[];
    float* sx = sm;
    float* sb = sx + HH * PITCH;
    float* s1 = sb + HH * PITCH;
    float* s2 = s1 + HH * PITCH;
    float* s3 = s2 + HH * PITCH;
    float* so = s3 + HH * PITCH;
    float* p0 = so + HH * PITCH;   // prev column, 130 entries (zero guards at 0 and 129)
    float* p1 = p0 + (HH + 2);     // next column (double buffer)

    const int t = threadIdx.x;              // t == h
    const long base = (long)blockIdx.x * (HH * WW);

    // zero both prev buffers (2 * 130 contiguous floats)
    for (int i = t; i < 2 * (HH + 2); i += 128) p0[i] = 0.0f;
    __syncthreads();

    float* prev = p0;
    float* nxt  = p1;
    float  pv   = 0.0f;   // this thread's own H[h, w-1] kept in register

    for (int tile = 0; tile < NTILES; ++tile) {
        const int w0 = tile * WT;

        // ---- coalesced float4 stage of 5 input tiles: 128 x 32 each ----
        // k indexes float4 groups: 128*32/4 = 1024 groups; 8 per thread.
        #pragma unroll
        for (int k = t; k < HH * WT / 4; k += 128) {
            const int row = k >> 3;         // /8 (8 float4 per row)
            const int col = (k & 7) << 2;   // *4
            const long g = base + (long)row * WW + w0 + col;
            const float4 vx = *(const float4*)(X  + g);
            const float4 vb = *(const float4*)(Bg + g);
            const float4 v1 = *(const float4*)(G1 + g);
            const float4 v2 = *(const float4*)(G2 + g);
            const float4 v3 = *(const float4*)(G3 + g);
            const int s = row * PITCH + col;
            sx[s+0]=vx.x; sx[s+1]=vx.y; sx[s+2]=vx.z; sx[s+3]=vx.w;
            sb[s+0]=vb.x; sb[s+1]=vb.y; sb[s+2]=vb.z; sb[s+3]=vb.w;
            s1[s+0]=v1.x; s1[s+1]=v1.y; s1[s+2]=v1.z; s1[s+3]=v1.w;
            s2[s+0]=v2.x; s2[s+1]=v2.y; s2[s+2]=v2.z; s2[s+3]=v2.w;
            s3[s+0]=v3.x; s3[s+1]=v3.y; s3[s+2]=v3.z; s3[s+3]=v3.w;
        }
        __syncthreads();

        // ---- sequential scan over the 32 columns of this tile ----
        #pragma unroll 4
        for (int wl = 0; wl < WT; ++wl) {
            const int s = t * PITCH + wl;
            // prev[t]   = H[h-1, w-1] (guard zero at t==0)
            // pv        = H[h,   w-1] (register)
            // prev[t+2] = H[h+1, w-1] (guard zero at t==127)
            float hv = sb[s] * sx[s];
            hv += s1[s] * prev[t];
            hv += s2[s] * pv;
            hv += s3[s] * prev[t + 2];
            nxt[t + 1] = hv;
            so[s] = hv;
            pv = hv;
            __syncthreads();
            float* tmp = prev; prev = nxt; nxt = tmp;
        }

        // ---- coalesced flush of the output tile ----
        for (int k = t; k < HH * WT; k += 128) {
            const int row = k >> 5;        // /32
            const int col = k & 31;
            O[base + (long)row * WW + w0 + col] = so[row * PITCH + col];
        }
        __syncthreads();   // protect so/input tiles before next stage
    }
}

extern "C" void kernel_launch(void* const* d_in, const int* in_sizes, int n_in,
                              void* d_out, int out_size)
{
    const float* X  = (const float*)d_in[0];
    const float* B  = (const float*)d_in[1];
    const float* G1 = (const float*)d_in[2];
    const float* G2 = (const float*)d_in[3];
    const float* G3 = (const float*)d_in[4];
    float* O = (float*)d_out;

    const int planes = 16 * 32;  // B*C
    const int smem_bytes = (6 * HH * PITCH + 2 * (HH + 2)) * sizeof(float);

    cudaFuncSetAttribute(gaterec2d_kernel,
                         cudaFuncAttributeMaxDynamicSharedMemorySize, smem_bytes);

    gaterec2d_kernel<<<planes, 128, smem_bytes>>>(X, B, G1, G2, G3, O);
}